// round 5
// baseline (speedup 1.0000x reference)
#include <cuda_runtime.h>

// ---------------------------------------------------------------------------
// SpanClassifier: two single-head attention logit maps with relative-position
// key bias.
//   q = (X @ Wq + bq) / sqrt(D); k = X @ Wk + bk
//   S[b,i,j] = q[b,i]·k[b,j] + (q[b,i]·rel[clip(j-i,-R,R)+R]) ; masked -> -1e18
// Stage 1: proj GEMMs (NN)      -> g_q[h], g_k[h]   (q pre-scaled by 1/32)
// Stage 2: qr = q @ rel^T (NT)  -> g_qr[h]
// Stage 3: scores (NT) + rel-bias gather + mask -> d_out (st half, ed half)
// All fp32 FFMA this round (accuracy-safe baseline); tensor-core (tcgen05
// bf16 hi/lo 3-pass) migration planned once profile data exists.
// ---------------------------------------------------------------------------

namespace cfg {
constexpr int Bn = 4, Tn = 2048, Dn = 1024, Rn = 64;
constexpr int NR = 2 * Rn + 1;     // 129
constexpr int Mrows = Bn * Tn;     // 8192
constexpr int BM = 128, BN = 128, BK = 16, TM = 8, TN = 8;
}
using namespace cfg;

// Scratch (static device allocations are allowed; cudaMalloc is not).
__device__ float g_q[2][Mrows * Dn];     // scaled queries, per head
__device__ float g_k[2][Mrows * Dn];     // keys, per head
__device__ float g_qr[2][Mrows * NR];    // q . rel_r, per head

// ---------------------------------------------------------------------------
// Stage 1: C[8192,1024] = X[8192,1024] @ W[1024,1024]; out = (C + bias)*alpha
// blockIdx.z: 0=st_q 1=st_k 2=ed_q 3=ed_k
// ---------------------------------------------------------------------------
__global__ __launch_bounds__(256, 2)
void proj_kernel(const float* __restrict__ X,
                 const float* __restrict__ Wq0, const float* __restrict__ bq0,
                 const float* __restrict__ Wk0, const float* __restrict__ bk0,
                 const float* __restrict__ Wq1, const float* __restrict__ bq1,
                 const float* __restrict__ Wk1, const float* __restrict__ bk1)
{
    __shared__ float As[BK][BM];
    __shared__ float Bs[BK][BN];

    const float* W; const float* bias; float* out; float alpha;
    switch (blockIdx.z) {
        case 0:  W = Wq0; bias = bq0; out = g_q[0]; alpha = 0.03125f; break;
        case 1:  W = Wk0; bias = bk0; out = g_k[0]; alpha = 1.0f;     break;
        case 2:  W = Wq1; bias = bq1; out = g_q[1]; alpha = 0.03125f; break;
        default: W = Wk1; bias = bk1; out = g_k[1]; alpha = 1.0f;     break;
    }

    const int tid = threadIdx.x;
    const int tx = tid & 15, ty = tid >> 4;
    const int rowBase = blockIdx.y * BM;
    const int colBase = blockIdx.x * BN;

    float acc[TM][TN] = {};

    for (int k0 = 0; k0 < Dn; k0 += BK) {
        // A tile (K-major source) -> transposed into As[k][m]
        #pragma unroll
        for (int l = 0; l < 2; l++) {
            int f = tid + l * 256;
            int r = f >> 2, c = (f & 3) << 2;
            float4 v = *reinterpret_cast<const float4*>(
                X + (size_t)(rowBase + r) * Dn + k0 + c);
            As[c + 0][r] = v.x; As[c + 1][r] = v.y;
            As[c + 2][r] = v.z; As[c + 3][r] = v.w;
        }
        // B tile (N-major source) -> direct Bs[k][n]
        #pragma unroll
        for (int l = 0; l < 2; l++) {
            int f = tid + l * 256;
            int kk = f >> 5, c = (f & 31) << 2;
            *reinterpret_cast<float4*>(&Bs[kk][c]) =
                *reinterpret_cast<const float4*>(
                    W + (size_t)(k0 + kk) * Dn + colBase + c);
        }
        __syncthreads();
        #pragma unroll
        for (int kk = 0; kk < BK; kk++) {
            float ra[TM], rb[TN];
            #pragma unroll
            for (int m = 0; m < TM; m++) ra[m] = As[kk][ty * TM + m];
            #pragma unroll
            for (int n = 0; n < TN; n++) rb[n] = Bs[kk][tx * TN + n];
            #pragma unroll
            for (int m = 0; m < TM; m++)
                #pragma unroll
                for (int n = 0; n < TN; n++)
                    acc[m][n] += ra[m] * rb[n];
        }
        __syncthreads();
    }

    #pragma unroll
    for (int m = 0; m < TM; m++) {
        int row = rowBase + ty * TM + m;
        #pragma unroll
        for (int n4 = 0; n4 < TN; n4 += 4) {
            int c0 = colBase + tx * TN + n4;
            float4 bv = *reinterpret_cast<const float4*>(bias + c0);
            float4 o;
            o.x = (acc[m][n4 + 0] + bv.x) * alpha;
            o.y = (acc[m][n4 + 1] + bv.y) * alpha;
            o.z = (acc[m][n4 + 2] + bv.z) * alpha;
            o.w = (acc[m][n4 + 3] + bv.w) * alpha;
            *reinterpret_cast<float4*>(out + (size_t)row * Dn + c0) = o;
        }
    }
}

// ---------------------------------------------------------------------------
// Stage 2: g_qr[h][m,r] = sum_d g_q[h][m,d] * rel[r,d]   (NT, N=129 bounded)
// blockIdx.z: head
// ---------------------------------------------------------------------------
__global__ __launch_bounds__(256, 2)
void qr_kernel(const float* __restrict__ rel0, const float* __restrict__ rel1)
{
    __shared__ float As[BK][BM];
    __shared__ float Bs[BK][BN];

    const int h = blockIdx.z;
    const float* Q = g_q[h];
    const float* Rel = h ? rel1 : rel0;
    float* out = g_qr[h];

    const int tid = threadIdx.x;
    const int tx = tid & 15, ty = tid >> 4;
    const int rowBase = blockIdx.y * BM;
    const int colBase = blockIdx.x * BN;

    float acc[TM][TN] = {};

    for (int k0 = 0; k0 < Dn; k0 += BK) {
        #pragma unroll
        for (int l = 0; l < 2; l++) {
            int f = tid + l * 256;
            int r = f >> 2, c = (f & 3) << 2;
            float4 v = *reinterpret_cast<const float4*>(
                Q + (size_t)(rowBase + r) * Dn + k0 + c);
            As[c + 0][r] = v.x; As[c + 1][r] = v.y;
            As[c + 2][r] = v.z; As[c + 3][r] = v.w;
        }
        #pragma unroll
        for (int l = 0; l < 2; l++) {
            int f = tid + l * 256;
            int r = f >> 2, c = (f & 3) << 2;
            int col = colBase + r;
            float4 v = make_float4(0.f, 0.f, 0.f, 0.f);
            if (col < NR)
                v = *reinterpret_cast<const float4*>(
                    Rel + (size_t)col * Dn + k0 + c);
            Bs[c + 0][r] = v.x; Bs[c + 1][r] = v.y;
            Bs[c + 2][r] = v.z; Bs[c + 3][r] = v.w;
        }
        __syncthreads();
        #pragma unroll
        for (int kk = 0; kk < BK; kk++) {
            float ra[TM], rb[TN];
            #pragma unroll
            for (int m = 0; m < TM; m++) ra[m] = As[kk][ty * TM + m];
            #pragma unroll
            for (int n = 0; n < TN; n++) rb[n] = Bs[kk][tx * TN + n];
            #pragma unroll
            for (int m = 0; m < TM; m++)
                #pragma unroll
                for (int n = 0; n < TN; n++)
                    acc[m][n] += ra[m] * rb[n];
        }
        __syncthreads();
    }

    #pragma unroll
    for (int m = 0; m < TM; m++) {
        int row = rowBase + ty * TM + m;
        #pragma unroll
        for (int n = 0; n < TN; n++) {
            int col = colBase + tx * TN + n;
            if (col < NR) out[(size_t)row * NR + col] = acc[m][n];
        }
    }
}

// ---------------------------------------------------------------------------
// Stage 3: S = q @ k^T + rel-bias gather + mask  (NT per batch/head)
// blockIdx.z in [0,8): h = z>>2 (0=st,1=ed), b = z&3
// ---------------------------------------------------------------------------
__global__ __launch_bounds__(256, 2)
void scores_kernel(const int* __restrict__ mask, float* __restrict__ gout)
{
    __shared__ float As[BK][BM];
    __shared__ float Bs[BK][BN];

    const int z = blockIdx.z;
    const int h = z >> 2;
    const int b = z & 3;

    const float* Q   = g_q[h]  + (size_t)b * Tn * Dn;
    const float* Kp  = g_k[h]  + (size_t)b * Tn * Dn;
    const float* QR  = g_qr[h] + (size_t)b * Tn * NR;
    const int*   Msk = mask    + (size_t)b * Tn * Tn;
    float*       Out = gout + (size_t)h * Bn * Tn * Tn + (size_t)b * Tn * Tn;

    const int tid = threadIdx.x;
    const int tx = tid & 15, ty = tid >> 4;
    const int rowBase = blockIdx.y * BM;
    const int colBase = blockIdx.x * BN;

    float acc[TM][TN] = {};

    for (int k0 = 0; k0 < Dn; k0 += BK) {
        #pragma unroll
        for (int l = 0; l < 2; l++) {
            int f = tid + l * 256;
            int r = f >> 2, c = (f & 3) << 2;
            float4 v = *reinterpret_cast<const float4*>(
                Q + (size_t)(rowBase + r) * Dn + k0 + c);
            As[c + 0][r] = v.x; As[c + 1][r] = v.y;
            As[c + 2][r] = v.z; As[c + 3][r] = v.w;
        }
        #pragma unroll
        for (int l = 0; l < 2; l++) {
            int f = tid + l * 256;
            int r = f >> 2, c = (f & 3) << 2;
            float4 v = *reinterpret_cast<const float4*>(
                Kp + (size_t)(colBase + r) * Dn + k0 + c);
            Bs[c + 0][r] = v.x; Bs[c + 1][r] = v.y;
            Bs[c + 2][r] = v.z; Bs[c + 3][r] = v.w;
        }
        __syncthreads();
        #pragma unroll
        for (int kk = 0; kk < BK; kk++) {
            float ra[TM], rb[TN];
            #pragma unroll
            for (int m = 0; m < TM; m++) ra[m] = As[kk][ty * TM + m];
            #pragma unroll
            for (int n = 0; n < TN; n++) rb[n] = Bs[kk][tx * TN + n];
            #pragma unroll
            for (int m = 0; m < TM; m++)
                #pragma unroll
                for (int n = 0; n < TN; n++)
                    acc[m][n] += ra[m] * rb[n];
        }
        __syncthreads();
    }

    // Epilogue: add qr[b,i,clip(j-i,-R,R)+R], apply mask, write.
    #pragma unroll
    for (int m = 0; m < TM; m++) {
        const int i = rowBase + ty * TM + m;
        const int ibase = i * Tn;
        const float* qr_row = QR + (size_t)i * NR;
        #pragma unroll
        for (int n4 = 0; n4 < TN; n4 += 4) {
            const int j0 = colBase + tx * TN + n4;
            float v[4];
            #pragma unroll
            for (int e = 0; e < 4; e++) {
                int d = j0 + e - i;
                d = d < -Rn ? -Rn : (d > Rn ? Rn : d);
                v[e] = acc[m][n4 + e] + qr_row[d + Rn];
            }
            int4 mk = *reinterpret_cast<const int4*>(Msk + ibase + j0);
            float4 o;
            o.x = mk.x ? v[0] : -1e18f;
            o.y = mk.y ? v[1] : -1e18f;
            o.z = mk.z ? v[2] : -1e18f;
            o.w = mk.w ? v[3] : -1e18f;
            *reinterpret_cast<float4*>(Out + ibase + j0) = o;
        }
    }
}

// ---------------------------------------------------------------------------
// Launch. Inputs (metadata order): repre, mask, st_Wq, st_bq, st_Wk, st_bk,
// st_rel, ed_Wq, ed_bq, ed_Wk, ed_bk, ed_rel. Output: [st | ed] fp32.
// ---------------------------------------------------------------------------
extern "C" void kernel_launch(void* const* d_in, const int* in_sizes, int n_in,
                              void* d_out, int out_size)
{
    (void)in_sizes; (void)n_in; (void)out_size;
    const float* repre  = (const float*)d_in[0];
    const int*   mask   = (const int*)  d_in[1];
    const float* st_Wq  = (const float*)d_in[2];
    const float* st_bq  = (const float*)d_in[3];
    const float* st_Wk  = (const float*)d_in[4];
    const float* st_bk  = (const float*)d_in[5];
    const float* st_rel = (const float*)d_in[6];
    const float* ed_Wq  = (const float*)d_in[7];
    const float* ed_bq  = (const float*)d_in[8];
    const float* ed_Wk  = (const float*)d_in[9];
    const float* ed_bk  = (const float*)d_in[10];
    const float* ed_rel = (const float*)d_in[11];
    float* out = (float*)d_out;

    dim3 blk(256);

    // Stage 1: projections (4 GEMMs via grid.z)
    proj_kernel<<<dim3(Dn / BN, Mrows / BM, 4), blk>>>(
        repre, st_Wq, st_bq, st_Wk, st_bk, ed_Wq, ed_bq, ed_Wk, ed_bk);

    // Stage 2: qr = q @ rel^T (2 heads via grid.z; N=129 -> 2 col tiles)
    qr_kernel<<<dim3((NR + BN - 1) / BN, Mrows / BM, 2), blk>>>(st_rel, ed_rel);

    // Stage 3: scores + rel bias + mask (8 batch*head slices via grid.z)
    scores_kernel<<<dim3(Tn / BN, Tn / BM, 8), blk>>>(mask, out);
}

// round 7
// speedup vs baseline: 1.2100x; 1.2100x over previous
#include <cuda_runtime.h>
#include <cuda_bf16.h>
#include <mma.h>
#include <cstdint>

using namespace nvcuda;

// ===========================================================================
// SpanClassifier via WMMA bf16 hi/lo 3-pass GEMMs (fp32 accumulate).
// (tcgen05 is unavailable: harness PTX target is bare sm_103, so only
//  family-portable tensor ops -- HMMA via WMMA -- are legal.)
//   q=(X Wq+bq)/32 ; k=X Wk+bk ; S=q k^T + gather(q rel^T) ; mask -> -1e18
// Every fp32 operand split x = hi + lo (bf16). One GEMM accumulates
// hi*hi + hi*lo + lo*hi over a 3x-K mainloop (lo*lo dropped, ~2^-16 rel).
// ===========================================================================

namespace cfg {
constexpr int Bn=4, Tn=2048, Dn=1024, Rn=64;
constexpr int NRpad=256, NRreal=129;
constexpr int Mrows=Bn*Tn;                    // 8192
constexpr int BM=128, BN=128, BK=32;
constexpr int NCH=3*(Dn/BK);                  // 96 chunks (3 passes x 32)
constexpr int LDS_AB=BK+8;                    // 40 bf16 (80B rows, 16B aligned)
constexpr int AB_BYTES=BM*LDS_AB*2;           // 10240 per tile
constexpr int LDS_C=BN+4;                     // 132 floats
constexpr int SMEM_BYTES=BM*LDS_C*4 + 2048;   // 69632 (> 4*AB_BYTES=40960)
}
using namespace cfg;

// ------------------------------- scratch -----------------------------------
__device__ __nv_bfloat16 g_Xhi[Mrows*Dn], g_Xlo[Mrows*Dn];
__device__ __nv_bfloat16 g_Wt_hi[4][Dn*Dn], g_Wt_lo[4][Dn*Dn];   // W^T [n][k]
__device__ __nv_bfloat16 g_relhi[2][NRpad*Dn], g_rello[2][NRpad*Dn];
__device__ __nv_bfloat16 g_qhi[2][Mrows*Dn], g_qlo[2][Mrows*Dn];
__device__ __nv_bfloat16 g_khi[2][Mrows*Dn], g_klo[2][Mrows*Dn];
__device__ float         g_qr2[2][Mrows*NRpad];

// ----------------------------- async helpers -------------------------------
__device__ __forceinline__ uint32_t smem_u32(const void* p){
    uint32_t a;
    asm("{ .reg .u64 t; cvta.to.shared.u64 t, %1; cvt.u32.u64 %0, t; }":"=r"(a):"l"(p));
    return a;
}
#define CP_ASYNC16(d,s) asm volatile("cp.async.cg.shared.global [%0], [%1], 16;"::"r"(d),"l"(s))
#define CP_COMMIT()     asm volatile("cp.async.commit_group;":::"memory")
#define CP_WAIT1()      asm volatile("cp.async.wait_group 1;":::"memory")
#define CP_WAIT0()      asm volatile("cp.async.wait_group 0;":::"memory")

// ---------------------------------------------------------------------------
// Shared mainloop: C[128,128] = sum over 96 BK=32 chunks of Atile @ Btile^T.
// A rows at Ah/Al (lda = Dn, K-major). B rows at Bh/Bl (K-major).
// Result staged in dynamic smem as float[128][132]; returns pointer.
// ---------------------------------------------------------------------------
__device__ __forceinline__ float* gemm_stage(
    const __nv_bfloat16* __restrict__ Ah, const __nv_bfloat16* __restrict__ Al,
    const __nv_bfloat16* __restrict__ Bh, const __nv_bfloat16* __restrict__ Bl)
{
    extern __shared__ char smem[];
    __nv_bfloat16* Asm[2] = { (__nv_bfloat16*)smem,
                              (__nv_bfloat16*)(smem + AB_BYTES) };
    __nv_bfloat16* Bsm[2] = { (__nv_bfloat16*)(smem + 2*AB_BYTES),
                              (__nv_bfloat16*)(smem + 3*AB_BYTES) };
    const uint32_t sm0 = smem_u32(smem);

    const int tid = threadIdx.x;
    const int wid = tid >> 5;
    const int warp_m = wid >> 2;          // 0..1  (64 rows each)
    const int warp_n = wid & 3;           // 0..3  (32 cols each)

    // cp.async mapping: 512 x 16B per tile; 2 per thread per matrix.
    const int r0 = tid >> 2;              // rows r0, r0+64
    const int sg = tid & 3;               // 16B segment within 64B row

    auto load_chunk = [&](int c, int b){
        const int pass = c >> 5;
        const int kof  = (c & 31) * BK + sg * 8;
        const __nv_bfloat16* A = (pass == 2) ? Al : Ah;
        const __nv_bfloat16* B = (pass == 1) ? Bl : Bh;
        const uint32_t dA = sm0 + b * AB_BYTES;
        const uint32_t dB = sm0 + (2 + b) * AB_BYTES;
        #pragma unroll
        for (int l = 0; l < 2; l++) {
            const int row = r0 + l * 64;
            CP_ASYNC16(dA + (uint32_t)(row*LDS_AB + sg*8)*2, A + (size_t)row*Dn + kof);
            CP_ASYNC16(dB + (uint32_t)(row*LDS_AB + sg*8)*2, B + (size_t)row*Dn + kof);
        }
    };

    wmma::fragment<wmma::accumulator, 16,16,16, float> acc[4][2];
    #pragma unroll
    for (int m = 0; m < 4; m++)
        #pragma unroll
        for (int n = 0; n < 2; n++) wmma::fill_fragment(acc[m][n], 0.0f);

    load_chunk(0, 0); CP_COMMIT();

    for (int i = 0; i < NCH; i++) {
        if (i + 1 < NCH) { load_chunk(i + 1, (i + 1) & 1); CP_COMMIT(); CP_WAIT1(); }
        else             { CP_WAIT0(); }
        __syncthreads();

        const __nv_bfloat16* As = Asm[i & 1] + warp_m * 64 * LDS_AB;
        const __nv_bfloat16* Bs = Bsm[i & 1] + warp_n * 32 * LDS_AB;
        #pragma unroll
        for (int ks = 0; ks < 2; ks++) {
            wmma::fragment<wmma::matrix_a, 16,16,16, __nv_bfloat16, wmma::row_major> fa[4];
            wmma::fragment<wmma::matrix_b, 16,16,16, __nv_bfloat16, wmma::col_major> fb[2];
            #pragma unroll
            for (int m = 0; m < 4; m++)
                wmma::load_matrix_sync(fa[m], As + m*16*LDS_AB + ks*16, LDS_AB);
            #pragma unroll
            for (int n = 0; n < 2; n++)
                wmma::load_matrix_sync(fb[n], Bs + n*16*LDS_AB + ks*16, LDS_AB);
            #pragma unroll
            for (int m = 0; m < 4; m++)
                #pragma unroll
                for (int n = 0; n < 2; n++)
                    wmma::mma_sync(acc[m][n], fa[m], fb[n], acc[m][n]);
        }
        __syncthreads();   // compute done before next iteration overwrites buf
    }

    // Stage C tile to smem (reuses the A/B buffers).
    float* Cs = (float*)smem;
    #pragma unroll
    for (int m = 0; m < 4; m++)
        #pragma unroll
        for (int n = 0; n < 2; n++)
            wmma::store_matrix_sync(
                Cs + (warp_m*64 + m*16) * LDS_C + warp_n*32 + n*16,
                acc[m][n], LDS_C, wmma::mem_row_major);
    __syncthreads();
    return Cs;
}

// ------------------------------ conversions --------------------------------
__global__ void convert_X(const float* __restrict__ s) {
    int i = blockIdx.x * 256 + threadIdx.x;              // over float2
    float2 v = reinterpret_cast<const float2*>(s)[i];
    __nv_bfloat16 h0 = __float2bfloat16(v.x), h1 = __float2bfloat16(v.y);
    reinterpret_cast<__nv_bfloat162*>(g_Xhi)[i] = __nv_bfloat162(h0, h1);
    reinterpret_cast<__nv_bfloat162*>(g_Xlo)[i] = __nv_bfloat162(
        __float2bfloat16(v.x - __bfloat162float(h0)),
        __float2bfloat16(v.y - __bfloat162float(h1)));
}

__global__ void convert_Wt(const float* __restrict__ W0, const float* __restrict__ W1,
                           const float* __restrict__ W2, const float* __restrict__ W3) {
    __shared__ float t[32][33];
    const int z = blockIdx.z;
    const float* W = (z==0)?W0:(z==1)?W1:(z==2)?W2:W3;
    const int x0 = blockIdx.x * 32, y0 = blockIdx.y * 32;    // x: n, y: k
    const int tx = threadIdx.x, ty = threadIdx.y;
    #pragma unroll
    for (int i = 0; i < 4; i++)
        t[ty + i*8][tx] = W[(size_t)(y0 + ty + i*8) * Dn + x0 + tx];
    __syncthreads();
    #pragma unroll
    for (int i = 0; i < 4; i++) {
        float v = t[tx][ty + i*8];
        __nv_bfloat16 h = __float2bfloat16(v);
        size_t o = (size_t)(x0 + ty + i*8) * Dn + y0 + tx;
        g_Wt_hi[z][o] = h;
        g_Wt_lo[z][o] = __float2bfloat16(v - __bfloat162float(h));
    }
}

__global__ void convert_rel(const float* __restrict__ r0, const float* __restrict__ r1) {
    const int h = blockIdx.y, row = blockIdx.x;
    const float* src = h ? r1 : r0;
    __nv_bfloat16* oh = g_relhi[h] + (size_t)row * Dn;
    __nv_bfloat16* ol = g_rello[h] + (size_t)row * Dn;
    for (int c = threadIdx.x; c < Dn; c += 256) {
        float v = (row < NRreal) ? src[(size_t)row * Dn + c] : 0.f;
        __nv_bfloat16 hh = __float2bfloat16(v);
        oh[c] = hh;
        ol[c] = __float2bfloat16(v - __bfloat162float(hh));
    }
}

// ------------------------------- GEMM kernels ------------------------------
__global__ __launch_bounds__(256)
void proj_mma(const float* __restrict__ bq0, const float* __restrict__ bk0,
              const float* __restrict__ bq1, const float* __restrict__ bk1) {
    const int z = blockIdx.z;
    const int rowBase = blockIdx.y * BM, colBase = blockIdx.x * BN;
    float* Cs = gemm_stage(g_Xhi + (size_t)rowBase * Dn, g_Xlo + (size_t)rowBase * Dn,
                           g_Wt_hi[z] + (size_t)colBase * Dn,
                           g_Wt_lo[z] + (size_t)colBase * Dn);
    const float* bias = (z==0)?bq0:(z==1)?bk0:(z==2)?bq1:bk1;
    const float alpha = (z & 1) ? 1.0f : 0.03125f;     // q gets 1/sqrt(1024)
    __nv_bfloat16* oh = (z==0)?g_qhi[0]:(z==1)?g_khi[0]:(z==2)?g_qhi[1]:g_khi[1];
    __nv_bfloat16* ol = (z==0)?g_qlo[0]:(z==1)?g_klo[0]:(z==2)?g_qlo[1]:g_klo[1];
    for (int it = threadIdx.x; it < BM * BN; it += 256) {
        const int row = it >> 7, c = it & 127;
        float v = (Cs[row * LDS_C + c] + bias[colBase + c]) * alpha;
        __nv_bfloat16 h = __float2bfloat16(v);
        size_t o = (size_t)(rowBase + row) * Dn + colBase + c;
        oh[o] = h;
        ol[o] = __float2bfloat16(v - __bfloat162float(h));
    }
}

__global__ __launch_bounds__(256)
void qr_mma() {
    const int h = blockIdx.z;
    const int rowBase = blockIdx.y * BM, colBase = blockIdx.x * BN;
    float* Cs = gemm_stage(g_qhi[h] + (size_t)rowBase * Dn,
                           g_qlo[h] + (size_t)rowBase * Dn,
                           g_relhi[h] + (size_t)colBase * Dn,
                           g_rello[h] + (size_t)colBase * Dn);
    for (int it = threadIdx.x; it < BM * BN; it += 256) {
        const int row = it >> 7, c = it & 127;
        g_qr2[h][(size_t)(rowBase + row) * NRpad + colBase + c] = Cs[row * LDS_C + c];
    }
}

__global__ __launch_bounds__(256)
void scores_mma(const int* __restrict__ mask, float* __restrict__ gout) {
    const int z = blockIdx.z, h = z >> 2, b = z & 3;
    const int rowBase = blockIdx.y * BM, colBase = blockIdx.x * BN;
    float* Cs = gemm_stage(g_qhi[h] + ((size_t)b * Tn + rowBase) * Dn,
                           g_qlo[h] + ((size_t)b * Tn + rowBase) * Dn,
                           g_khi[h] + ((size_t)b * Tn + colBase) * Dn,
                           g_klo[h] + ((size_t)b * Tn + colBase) * Dn);
    const float* QR  = g_qr2[h] + (size_t)b * Tn * NRpad;
    const int*   Msk = mask + (size_t)b * Tn * Tn;
    float*       Out = gout + (size_t)h * Bn * Tn * Tn + (size_t)b * Tn * Tn;
    for (int it = threadIdx.x; it < BM * BN; it += 256) {
        const int row = it >> 7, c = it & 127;
        const int i = rowBase + row, j = colBase + c;
        int d = j - i; d = d < -Rn ? -Rn : (d > Rn ? Rn : d);
        float v = Cs[row * LDS_C + c] + QR[(size_t)i * NRpad + d + Rn];
        Out[(size_t)i * Tn + j] = Msk[(size_t)i * Tn + j] ? v : -1e18f;
    }
}

// --------------------------------- launch ----------------------------------
extern "C" void kernel_launch(void* const* d_in, const int* in_sizes, int n_in,
                              void* d_out, int out_size)
{
    (void)in_sizes; (void)n_in; (void)out_size;
    const float* repre  = (const float*)d_in[0];
    const int*   mask   = (const int*)  d_in[1];
    const float* st_Wq  = (const float*)d_in[2];
    const float* st_bq  = (const float*)d_in[3];
    const float* st_Wk  = (const float*)d_in[4];
    const float* st_bk  = (const float*)d_in[5];
    const float* st_rel = (const float*)d_in[6];
    const float* ed_Wq  = (const float*)d_in[7];
    const float* ed_bq  = (const float*)d_in[8];
    const float* ed_Wk  = (const float*)d_in[9];
    const float* ed_bk  = (const float*)d_in[10];
    const float* ed_rel = (const float*)d_in[11];
    float* out = (float*)d_out;

    static bool attr_set = false;
    if (!attr_set) {
        cudaFuncSetAttribute(proj_mma,   cudaFuncAttributeMaxDynamicSharedMemorySize, SMEM_BYTES);
        cudaFuncSetAttribute(qr_mma,     cudaFuncAttributeMaxDynamicSharedMemorySize, SMEM_BYTES);
        cudaFuncSetAttribute(scores_mma, cudaFuncAttributeMaxDynamicSharedMemorySize, SMEM_BYTES);
        attr_set = true;
    }

    convert_X  <<<Mrows * Dn / 512, 256>>>(repre);
    convert_Wt <<<dim3(32, 32, 4), dim3(32, 8)>>>(st_Wq, st_Wk, ed_Wq, ed_Wk);
    convert_rel<<<dim3(NRpad, 2), 256>>>(st_rel, ed_rel);

    proj_mma  <<<dim3(Dn/BN, Mrows/BM, 4), 256, SMEM_BYTES>>>(st_bq, st_bk, ed_bq, ed_bk);
    qr_mma    <<<dim3(NRpad/BN, Mrows/BM, 2), 256, SMEM_BYTES>>>();
    scores_mma<<<dim3(Tn/BN, Tn/BM, 8),    256, SMEM_BYTES>>>(mask, out);
}

// round 8
// speedup vs baseline: 1.8544x; 1.5326x over previous
#include <cuda_runtime.h>
#include <cuda_bf16.h>
#include <mma.h>
#include <cstdint>

using namespace nvcuda;

// ===========================================================================
// SpanClassifier via WMMA bf16 hi/lo 3-pass GEMMs (fp32 accumulate).
// (tcgen05 unavailable: harness PTX target is bare sm_103.)
//   q=(X Wq+bq)/32 ; k=X Wk+bk ; S=q k^T + gather(q rel^T) ; mask -> -1e18
// fp32 operands split x = hi + lo (bf16); one GEMM accumulates
// hi*hi + hi*lo + lo*hi over a 3x-K mainloop (lo*lo dropped, ~2^-16 rel).
// R8: 4-stage cp.async pipeline, ONE __syncthreads per chunk, 2 CTAs/SM.
// ===========================================================================

namespace cfg {
constexpr int Bn=4, Tn=2048, Dn=1024, Rn=64;
constexpr int NRpad=256, NRreal=129;
constexpr int Mrows=Bn*Tn;                    // 8192
constexpr int BM=128, BN=128, BK=32;
constexpr int NCH=3*(Dn/BK);                  // 96 chunks (3 passes x 32)
constexpr int STAGES=4;
constexpr int LDS_AB=BK+8;                    // 40 bf16 (80B rows)
constexpr int AB_BYTES=BM*LDS_AB*2;           // 10240 per matrix tile
constexpr int STAGE_BYTES=2*AB_BYTES;         // 20480 (A+B)
constexpr int LDS_C=BN+4;                     // 132 floats
constexpr int SMEM_BYTES=STAGES*STAGE_BYTES;  // 81920 (> C stage 67584)
}
using namespace cfg;

// ------------------------------- scratch -----------------------------------
__device__ __nv_bfloat16 g_Xhi[Mrows*Dn], g_Xlo[Mrows*Dn];
__device__ __nv_bfloat16 g_Wt_hi[4][Dn*Dn], g_Wt_lo[4][Dn*Dn];   // W^T [n][k]
__device__ __nv_bfloat16 g_relhi[2][NRpad*Dn], g_rello[2][NRpad*Dn];
__device__ __nv_bfloat16 g_qhi[2][Mrows*Dn], g_qlo[2][Mrows*Dn];
__device__ __nv_bfloat16 g_khi[2][Mrows*Dn], g_klo[2][Mrows*Dn];
__device__ float         g_qr2[2][Mrows*NRpad];

// ----------------------------- async helpers -------------------------------
__device__ __forceinline__ uint32_t smem_u32(const void* p){
    uint32_t a;
    asm("{ .reg .u64 t; cvta.to.shared.u64 t, %1; cvt.u32.u64 %0, t; }":"=r"(a):"l"(p));
    return a;
}
#define CP_ASYNC16(d,s) asm volatile("cp.async.cg.shared.global [%0], [%1], 16;"::"r"(d),"l"(s))
#define CP_COMMIT()     asm volatile("cp.async.commit_group;":::"memory")
#define CP_WAIT2()      asm volatile("cp.async.wait_group 2;":::"memory")
#define CP_WAIT0()      asm volatile("cp.async.wait_group 0;":::"memory")

// ---------------------------------------------------------------------------
// Mainloop: C[128,128] = sum over 96 BK=32 chunks of Atile @ Btile^T.
// 4-stage cp.async ring, single __syncthreads per chunk.
// Result staged in smem as float[128][132]; returns pointer.
// ---------------------------------------------------------------------------
__device__ __forceinline__ float* gemm_stage(
    const __nv_bfloat16* __restrict__ Ah, const __nv_bfloat16* __restrict__ Al,
    const __nv_bfloat16* __restrict__ Bh, const __nv_bfloat16* __restrict__ Bl)
{
    extern __shared__ char smem[];
    const uint32_t sm0 = smem_u32(smem);

    const int tid = threadIdx.x;
    const int wid = tid >> 5;
    const int warp_m = wid >> 2;          // 0..1  (64 rows)
    const int warp_n = wid & 3;           // 0..3  (32 cols)

    // cp.async mapping: per matrix 512 x 16B; 2 per thread per matrix.
    const int r0 = tid >> 2;              // rows r0, r0+64
    const int sg = tid & 3;               // 16B segment within 64B row

    auto load_chunk = [&](int c){
        const int s    = c & (STAGES - 1);
        const int pass = c >> 5;
        const int kof  = (c & 31) * BK + sg * 8;
        const __nv_bfloat16* A = (pass == 2) ? Al : Ah;
        const __nv_bfloat16* B = (pass == 1) ? Bl : Bh;
        const uint32_t dA = sm0 + s * STAGE_BYTES;
        const uint32_t dB = dA + AB_BYTES;
        #pragma unroll
        for (int l = 0; l < 2; l++) {
            const int row = r0 + l * 64;
            CP_ASYNC16(dA + (uint32_t)(row*LDS_AB + sg*8)*2, A + (size_t)row*Dn + kof);
            CP_ASYNC16(dB + (uint32_t)(row*LDS_AB + sg*8)*2, B + (size_t)row*Dn + kof);
        }
    };

    wmma::fragment<wmma::accumulator, 16,16,16, float> acc[4][2];
    #pragma unroll
    for (int m = 0; m < 4; m++)
        #pragma unroll
        for (int n = 0; n < 2; n++) wmma::fill_fragment(acc[m][n], 0.0f);

    // Prologue: stages 0..2 in flight (3 groups).
    #pragma unroll
    for (int c = 0; c < STAGES - 1; c++) { load_chunk(c); CP_COMMIT(); }

    for (int i = 0; i < NCH; i++) {
        CP_WAIT2();          // group i complete -> chunk i resident
        __syncthreads();     // all warps done with compute(i-1) (buffer (i-1)&3)
        if (i + STAGES - 1 < NCH) load_chunk(i + STAGES - 1);
        CP_COMMIT();         // empty groups at tail keep counting uniform

        const int s = i & (STAGES - 1);
        const __nv_bfloat16* As =
            (const __nv_bfloat16*)(smem + s * STAGE_BYTES) + warp_m * 64 * LDS_AB;
        const __nv_bfloat16* Bs =
            (const __nv_bfloat16*)(smem + s * STAGE_BYTES + AB_BYTES) + warp_n * 32 * LDS_AB;
        #pragma unroll
        for (int ks = 0; ks < 2; ks++) {
            wmma::fragment<wmma::matrix_a, 16,16,16, __nv_bfloat16, wmma::row_major> fa[4];
            wmma::fragment<wmma::matrix_b, 16,16,16, __nv_bfloat16, wmma::col_major> fb[2];
            #pragma unroll
            for (int m = 0; m < 4; m++)
                wmma::load_matrix_sync(fa[m], As + m*16*LDS_AB + ks*16, LDS_AB);
            #pragma unroll
            for (int n = 0; n < 2; n++)
                wmma::load_matrix_sync(fb[n], Bs + n*16*LDS_AB + ks*16, LDS_AB);
            #pragma unroll
            for (int m = 0; m < 4; m++)
                #pragma unroll
                for (int n = 0; n < 2; n++)
                    wmma::mma_sync(acc[m][n], fa[m], fb[n], acc[m][n]);
        }
    }

    CP_WAIT0();
    __syncthreads();         // all compute done before C overwrites buffers

    float* Cs = (float*)smem;
    #pragma unroll
    for (int m = 0; m < 4; m++)
        #pragma unroll
        for (int n = 0; n < 2; n++)
            wmma::store_matrix_sync(
                Cs + (warp_m*64 + m*16) * LDS_C + warp_n*32 + n*16,
                acc[m][n], LDS_C, wmma::mem_row_major);
    __syncthreads();
    return Cs;
}

// ------------------------------ conversions --------------------------------
__global__ void convert_X(const float* __restrict__ s) {
    int i = blockIdx.x * 256 + threadIdx.x;              // over float2
    float2 v = reinterpret_cast<const float2*>(s)[i];
    __nv_bfloat16 h0 = __float2bfloat16(v.x), h1 = __float2bfloat16(v.y);
    reinterpret_cast<__nv_bfloat162*>(g_Xhi)[i] = __nv_bfloat162(h0, h1);
    reinterpret_cast<__nv_bfloat162*>(g_Xlo)[i] = __nv_bfloat162(
        __float2bfloat16(v.x - __bfloat162float(h0)),
        __float2bfloat16(v.y - __bfloat162float(h1)));
}

__global__ void convert_Wt(const float* __restrict__ W0, const float* __restrict__ W1,
                           const float* __restrict__ W2, const float* __restrict__ W3) {
    __shared__ float t[32][33];
    const int z = blockIdx.z;
    const float* W = (z==0)?W0:(z==1)?W1:(z==2)?W2:W3;
    const int x0 = blockIdx.x * 32, y0 = blockIdx.y * 32;    // x: n, y: k
    const int tx = threadIdx.x, ty = threadIdx.y;
    #pragma unroll
    for (int i = 0; i < 4; i++)
        t[ty + i*8][tx] = W[(size_t)(y0 + ty + i*8) * Dn + x0 + tx];
    __syncthreads();
    #pragma unroll
    for (int i = 0; i < 4; i++) {
        float v = t[tx][ty + i*8];
        __nv_bfloat16 h = __float2bfloat16(v);
        size_t o = (size_t)(x0 + ty + i*8) * Dn + y0 + tx;
        g_Wt_hi[z][o] = h;
        g_Wt_lo[z][o] = __float2bfloat16(v - __bfloat162float(h));
    }
}

__global__ void convert_rel(const float* __restrict__ r0, const float* __restrict__ r1) {
    const int h = blockIdx.y, row = blockIdx.x;
    const float* src = h ? r1 : r0;
    __nv_bfloat16* oh = g_relhi[h] + (size_t)row * Dn;
    __nv_bfloat16* ol = g_rello[h] + (size_t)row * Dn;
    for (int c = threadIdx.x; c < Dn; c += 256) {
        float v = (row < NRreal) ? src[(size_t)row * Dn + c] : 0.f;
        __nv_bfloat16 hh = __float2bfloat16(v);
        oh[c] = hh;
        ol[c] = __float2bfloat16(v - __bfloat162float(hh));
    }
}

// ------------------------------- GEMM kernels ------------------------------
__global__ __launch_bounds__(256, 2)
void proj_mma(const float* __restrict__ bq0, const float* __restrict__ bk0,
              const float* __restrict__ bq1, const float* __restrict__ bk1) {
    const int z = blockIdx.z;
    const int rowBase = blockIdx.y * BM, colBase = blockIdx.x * BN;
    float* Cs = gemm_stage(g_Xhi + (size_t)rowBase * Dn, g_Xlo + (size_t)rowBase * Dn,
                           g_Wt_hi[z] + (size_t)colBase * Dn,
                           g_Wt_lo[z] + (size_t)colBase * Dn);
    const float* bias = (z==0)?bq0:(z==1)?bk0:(z==2)?bq1:bk1;
    const float alpha = (z & 1) ? 1.0f : 0.03125f;     // q gets 1/sqrt(1024)
    __nv_bfloat16* oh = (z==0)?g_qhi[0]:(z==1)?g_khi[0]:(z==2)?g_qhi[1]:g_khi[1];
    __nv_bfloat16* ol = (z==0)?g_qlo[0]:(z==1)?g_klo[0]:(z==2)?g_qlo[1]:g_klo[1];
    for (int it = threadIdx.x; it < BM * BN; it += 256) {
        const int row = it >> 7, c = it & 127;
        float v = (Cs[row * LDS_C + c] + bias[colBase + c]) * alpha;
        __nv_bfloat16 h = __float2bfloat16(v);
        size_t o = (size_t)(rowBase + row) * Dn + colBase + c;
        oh[o] = h;
        ol[o] = __float2bfloat16(v - __bfloat162float(h));
    }
}

__global__ __launch_bounds__(256, 2)
void qr_mma() {
    const int h = blockIdx.z;
    const int rowBase = blockIdx.y * BM, colBase = blockIdx.x * BN;
    float* Cs = gemm_stage(g_qhi[h] + (size_t)rowBase * Dn,
                           g_qlo[h] + (size_t)rowBase * Dn,
                           g_relhi[h] + (size_t)colBase * Dn,
                           g_rello[h] + (size_t)colBase * Dn);
    for (int it = threadIdx.x; it < BM * BN; it += 256) {
        const int row = it >> 7, c = it & 127;
        g_qr2[h][(size_t)(rowBase + row) * NRpad + colBase + c] = Cs[row * LDS_C + c];
    }
}

__global__ __launch_bounds__(256, 2)
void scores_mma(const int* __restrict__ mask, float* __restrict__ gout) {
    const int z = blockIdx.z, h = z >> 2, b = z & 3;
    const int rowBase = blockIdx.y * BM, colBase = blockIdx.x * BN;
    float* Cs = gemm_stage(g_qhi[h] + ((size_t)b * Tn + rowBase) * Dn,
                           g_qlo[h] + ((size_t)b * Tn + rowBase) * Dn,
                           g_khi[h] + ((size_t)b * Tn + colBase) * Dn,
                           g_klo[h] + ((size_t)b * Tn + colBase) * Dn);
    const float* QR  = g_qr2[h] + (size_t)b * Tn * NRpad;
    const int*   Msk = mask + (size_t)b * Tn * Tn;
    float*       Out = gout + (size_t)h * Bn * Tn * Tn + (size_t)b * Tn * Tn;
    for (int it = threadIdx.x; it < BM * BN; it += 256) {
        const int row = it >> 7, c = it & 127;
        const int i = rowBase + row, j = colBase + c;
        int d = j - i; d = d < -Rn ? -Rn : (d > Rn ? Rn : d);
        float v = Cs[row * LDS_C + c] + QR[(size_t)i * NRpad + d + Rn];
        Out[(size_t)i * Tn + j] = Msk[(size_t)i * Tn + j] ? v : -1e18f;
    }
}

// --------------------------------- launch ----------------------------------
extern "C" void kernel_launch(void* const* d_in, const int* in_sizes, int n_in,
                              void* d_out, int out_size)
{
    (void)in_sizes; (void)n_in; (void)out_size;
    const float* repre  = (const float*)d_in[0];
    const int*   mask   = (const int*)  d_in[1];
    const float* st_Wq  = (const float*)d_in[2];
    const float* st_bq  = (const float*)d_in[3];
    const float* st_Wk  = (const float*)d_in[4];
    const float* st_bk  = (const float*)d_in[5];
    const float* st_rel = (const float*)d_in[6];
    const float* ed_Wq  = (const float*)d_in[7];
    const float* ed_bq  = (const float*)d_in[8];
    const float* ed_Wk  = (const float*)d_in[9];
    const float* ed_bk  = (const float*)d_in[10];
    const float* ed_rel = (const float*)d_in[11];
    float* out = (float*)d_out;

    static bool attr_set = false;
    if (!attr_set) {
        cudaFuncSetAttribute(proj_mma,   cudaFuncAttributeMaxDynamicSharedMemorySize, SMEM_BYTES);
        cudaFuncSetAttribute(qr_mma,     cudaFuncAttributeMaxDynamicSharedMemorySize, SMEM_BYTES);
        cudaFuncSetAttribute(scores_mma, cudaFuncAttributeMaxDynamicSharedMemorySize, SMEM_BYTES);
        attr_set = true;
    }

    convert_X  <<<Mrows * Dn / 512, 256>>>(repre);
    convert_Wt <<<dim3(32, 32, 4), dim3(32, 8)>>>(st_Wq, st_Wk, ed_Wq, ed_Wk);
    convert_rel<<<dim3(NRpad, 2), 256>>>(st_rel, ed_rel);

    proj_mma  <<<dim3(Dn/BN, Mrows/BM, 4), 256, SMEM_BYTES>>>(st_bq, st_bk, ed_bq, ed_bk);
    qr_mma    <<<dim3(NRpad/BN, Mrows/BM, 2), 256, SMEM_BYTES>>>();
    scores_mma<<<dim3(Tn/BN, Tn/BM, 8),    256, SMEM_BYTES>>>(mask, out);
}

// round 9
// speedup vs baseline: 2.0713x; 1.1170x over previous
#include <cuda_runtime.h>
#include <cuda_bf16.h>
#include <mma.h>
#include <cstdint>

using namespace nvcuda;

// ===========================================================================
// SpanClassifier via WMMA bf16 hi/lo 3-pass GEMMs (fp32 accumulate).
// (tcgen05 unavailable: harness PTX target is bare sm_103.)
//   q=(X Wq+bq)/32 ; k=X Wk+bk ; S=q k^T + gather(q rel^T) ; mask -> -1e18
// fp32 operands split x = hi + lo (bf16); one GEMM accumulates
// hi*hi + hi*lo + lo*hi over a 3x-K mainloop (lo*lo dropped, ~2^-16 rel).
// R9: BK=64 (48 chunks, half the barriers), 3-stage cp.async ring,
//     one __syncthreads per chunk, 2 CTAs/SM.
// ===========================================================================

namespace cfg {
constexpr int Bn=4, Tn=2048, Dn=1024, Rn=64;
constexpr int NRpad=256, NRreal=129;
constexpr int Mrows=Bn*Tn;                    // 8192
constexpr int BM=128, BN=128, BK=64;
constexpr int NCH=3*(Dn/BK);                  // 48 chunks (3 passes x 16)
constexpr int STAGES=3;
constexpr int LDS_AB=BK+8;                    // 72 bf16 (144B rows)
constexpr int AB_BYTES=BM*LDS_AB*2;           // 18432 per matrix tile
constexpr int STAGE_BYTES=2*AB_BYTES;         // 36864 (A+B)
constexpr int LDS_C=BN+4;                     // 132 floats
constexpr int SMEM_BYTES=STAGES*STAGE_BYTES;  // 110592 (> C stage 67584)
}
using namespace cfg;

// ------------------------------- scratch -----------------------------------
__device__ __nv_bfloat16 g_Xhi[Mrows*Dn], g_Xlo[Mrows*Dn];
__device__ __nv_bfloat16 g_Wt_hi[4][Dn*Dn], g_Wt_lo[4][Dn*Dn];   // W^T [n][k]
__device__ __nv_bfloat16 g_relhi[2][NRpad*Dn], g_rello[2][NRpad*Dn];
__device__ __nv_bfloat16 g_qhi[2][Mrows*Dn], g_qlo[2][Mrows*Dn];
__device__ __nv_bfloat16 g_khi[2][Mrows*Dn], g_klo[2][Mrows*Dn];
__device__ float         g_qr2[2][Mrows*NRpad];

// ----------------------------- async helpers -------------------------------
__device__ __forceinline__ uint32_t smem_u32(const void* p){
    uint32_t a;
    asm("{ .reg .u64 t; cvta.to.shared.u64 t, %1; cvt.u32.u64 %0, t; }":"=r"(a):"l"(p));
    return a;
}
#define CP_ASYNC16(d,s) asm volatile("cp.async.cg.shared.global [%0], [%1], 16;"::"r"(d),"l"(s))
#define CP_COMMIT()     asm volatile("cp.async.commit_group;":::"memory")
#define CP_WAIT1()      asm volatile("cp.async.wait_group 1;":::"memory")
#define CP_WAIT0()      asm volatile("cp.async.wait_group 0;":::"memory")

// ---------------------------------------------------------------------------
// Mainloop: C[128,128] = sum over 48 BK=64 chunks of Atile @ Btile^T.
// 3-stage cp.async ring, single __syncthreads per chunk.
// Result staged in smem as float[128][132]; returns pointer.
// ---------------------------------------------------------------------------
__device__ __forceinline__ float* gemm_stage(
    const __nv_bfloat16* __restrict__ Ah, const __nv_bfloat16* __restrict__ Al,
    const __nv_bfloat16* __restrict__ Bh, const __nv_bfloat16* __restrict__ Bl)
{
    extern __shared__ char smem[];
    const uint32_t sm0 = smem_u32(smem);

    const int tid = threadIdx.x;
    const int wid = tid >> 5;
    const int warp_m = wid >> 2;          // 0..1  (64 rows)
    const int warp_n = wid & 3;           // 0..3  (32 cols)

    // cp.async mapping: per matrix 128 rows x 8 x 16B segments = 1024 segs;
    // 4 per thread, consecutive tids hit consecutive segments (coalesced).
    auto load_chunk = [&](int c){
        const int s    = c % STAGES;
        const int pass = c >> 4;
        const int kof  = (c & 15) * BK;
        const __nv_bfloat16* A = (pass == 2) ? Al : Ah;
        const __nv_bfloat16* B = (pass == 1) ? Bl : Bh;
        const uint32_t dA = sm0 + s * STAGE_BYTES;
        const uint32_t dB = dA + AB_BYTES;
        #pragma unroll
        for (int l = 0; l < 4; l++) {
            const int f   = tid + l * 256;
            const int row = f >> 3;
            const int sg  = f & 7;
            const uint32_t so = (uint32_t)row * (LDS_AB*2) + sg * 16;
            const size_t   go = (size_t)row * Dn + kof + sg * 8;
            CP_ASYNC16(dA + so, A + go);
            CP_ASYNC16(dB + so, B + go);
        }
    };

    wmma::fragment<wmma::accumulator, 16,16,16, float> acc[4][2];
    #pragma unroll
    for (int m = 0; m < 4; m++)
        #pragma unroll
        for (int n = 0; n < 2; n++) wmma::fill_fragment(acc[m][n], 0.0f);

    // Prologue: 2 stages in flight.
    load_chunk(0); CP_COMMIT();
    load_chunk(1); CP_COMMIT();

    for (int i = 0; i < NCH; i++) {
        CP_WAIT1();          // chunk i resident (i+1 may be pending)
        __syncthreads();     // all warps done with compute(i-1)
        if (i + 2 < NCH) load_chunk(i + 2);
        CP_COMMIT();         // empty groups at tail keep counting uniform

        const int s = i % STAGES;
        const __nv_bfloat16* As =
            (const __nv_bfloat16*)(smem + s * STAGE_BYTES) + warp_m * 64 * LDS_AB;
        const __nv_bfloat16* Bs =
            (const __nv_bfloat16*)(smem + s * STAGE_BYTES + AB_BYTES) + warp_n * 32 * LDS_AB;
        #pragma unroll
        for (int ks = 0; ks < 4; ks++) {
            wmma::fragment<wmma::matrix_a, 16,16,16, __nv_bfloat16, wmma::row_major> fa[4];
            wmma::fragment<wmma::matrix_b, 16,16,16, __nv_bfloat16, wmma::col_major> fb[2];
            #pragma unroll
            for (int m = 0; m < 4; m++)
                wmma::load_matrix_sync(fa[m], As + m*16*LDS_AB + ks*16, LDS_AB);
            #pragma unroll
            for (int n = 0; n < 2; n++)
                wmma::load_matrix_sync(fb[n], Bs + n*16*LDS_AB + ks*16, LDS_AB);
            #pragma unroll
            for (int m = 0; m < 4; m++)
                #pragma unroll
                for (int n = 0; n < 2; n++)
                    wmma::mma_sync(acc[m][n], fa[m], fb[n], acc[m][n]);
        }
    }

    CP_WAIT0();
    __syncthreads();         // all compute done before C overwrites buffers

    float* Cs = (float*)smem;
    #pragma unroll
    for (int m = 0; m < 4; m++)
        #pragma unroll
        for (int n = 0; n < 2; n++)
            wmma::store_matrix_sync(
                Cs + (warp_m*64 + m*16) * LDS_C + warp_n*32 + n*16,
                acc[m][n], LDS_C, wmma::mem_row_major);
    __syncthreads();
    return Cs;
}

// ------------------------------ conversions --------------------------------
__global__ void convert_X(const float* __restrict__ s) {
    int i = blockIdx.x * 256 + threadIdx.x;              // over float2
    float2 v = reinterpret_cast<const float2*>(s)[i];
    __nv_bfloat16 h0 = __float2bfloat16(v.x), h1 = __float2bfloat16(v.y);
    reinterpret_cast<__nv_bfloat162*>(g_Xhi)[i] = __nv_bfloat162(h0, h1);
    reinterpret_cast<__nv_bfloat162*>(g_Xlo)[i] = __nv_bfloat162(
        __float2bfloat16(v.x - __bfloat162float(h0)),
        __float2bfloat16(v.y - __bfloat162float(h1)));
}

__global__ void convert_Wt(const float* __restrict__ W0, const float* __restrict__ W1,
                           const float* __restrict__ W2, const float* __restrict__ W3) {
    __shared__ float t[32][33];
    const int z = blockIdx.z;
    const float* W = (z==0)?W0:(z==1)?W1:(z==2)?W2:W3;
    const int x0 = blockIdx.x * 32, y0 = blockIdx.y * 32;    // x: n, y: k
    const int tx = threadIdx.x, ty = threadIdx.y;
    #pragma unroll
    for (int i = 0; i < 4; i++)
        t[ty + i*8][tx] = W[(size_t)(y0 + ty + i*8) * Dn + x0 + tx];
    __syncthreads();
    #pragma unroll
    for (int i = 0; i < 4; i++) {
        float v = t[tx][ty + i*8];
        __nv_bfloat16 h = __float2bfloat16(v);
        size_t o = (size_t)(x0 + ty + i*8) * Dn + y0 + tx;
        g_Wt_hi[z][o] = h;
        g_Wt_lo[z][o] = __float2bfloat16(v - __bfloat162float(h));
    }
}

__global__ void convert_rel(const float* __restrict__ r0, const float* __restrict__ r1) {
    const int h = blockIdx.y, row = blockIdx.x;
    const float* src = h ? r1 : r0;
    __nv_bfloat16* oh = g_relhi[h] + (size_t)row * Dn;
    __nv_bfloat16* ol = g_rello[h] + (size_t)row * Dn;
    for (int c = threadIdx.x; c < Dn; c += 256) {
        float v = (row < NRreal) ? src[(size_t)row * Dn + c] : 0.f;
        __nv_bfloat16 hh = __float2bfloat16(v);
        oh[c] = hh;
        ol[c] = __float2bfloat16(v - __bfloat162float(hh));
    }
}

// ------------------------------- GEMM kernels ------------------------------
__global__ __launch_bounds__(256, 2)
void proj_mma(const float* __restrict__ bq0, const float* __restrict__ bk0,
              const float* __restrict__ bq1, const float* __restrict__ bk1) {
    const int z = blockIdx.z;
    const int rowBase = blockIdx.y * BM, colBase = blockIdx.x * BN;
    float* Cs = gemm_stage(g_Xhi + (size_t)rowBase * Dn, g_Xlo + (size_t)rowBase * Dn,
                           g_Wt_hi[z] + (size_t)colBase * Dn,
                           g_Wt_lo[z] + (size_t)colBase * Dn);
    const float* bias = (z==0)?bq0:(z==1)?bk0:(z==2)?bq1:bk1;
    const float alpha = (z & 1) ? 1.0f : 0.03125f;     // q gets 1/sqrt(1024)
    __nv_bfloat16* oh = (z==0)?g_qhi[0]:(z==1)?g_khi[0]:(z==2)?g_qhi[1]:g_khi[1];
    __nv_bfloat16* ol = (z==0)?g_qlo[0]:(z==1)?g_klo[0]:(z==2)?g_qlo[1]:g_klo[1];
    for (int it = threadIdx.x; it < BM * BN; it += 256) {
        const int row = it >> 7, c = it & 127;
        float v = (Cs[row * LDS_C + c] + bias[colBase + c]) * alpha;
        __nv_bfloat16 h = __float2bfloat16(v);
        size_t o = (size_t)(rowBase + row) * Dn + colBase + c;
        oh[o] = h;
        ol[o] = __float2bfloat16(v - __bfloat162float(h));
    }
}

__global__ __launch_bounds__(256, 2)
void qr_mma() {
    const int h = blockIdx.z;
    const int rowBase = blockIdx.y * BM, colBase = blockIdx.x * BN;
    float* Cs = gemm_stage(g_qhi[h] + (size_t)rowBase * Dn,
                           g_qlo[h] + (size_t)rowBase * Dn,
                           g_relhi[h] + (size_t)colBase * Dn,
                           g_rello[h] + (size_t)colBase * Dn);
    for (int it = threadIdx.x; it < BM * BN; it += 256) {
        const int row = it >> 7, c = it & 127;
        g_qr2[h][(size_t)(rowBase + row) * NRpad + colBase + c] = Cs[row * LDS_C + c];
    }
}

__global__ __launch_bounds__(256, 2)
void scores_mma(const int* __restrict__ mask, float* __restrict__ gout) {
    const int z = blockIdx.z, h = z >> 2, b = z & 3;
    const int rowBase = blockIdx.y * BM, colBase = blockIdx.x * BN;
    float* Cs = gemm_stage(g_qhi[h] + ((size_t)b * Tn + rowBase) * Dn,
                           g_qlo[h] + ((size_t)b * Tn + rowBase) * Dn,
                           g_khi[h] + ((size_t)b * Tn + colBase) * Dn,
                           g_klo[h] + ((size_t)b * Tn + colBase) * Dn);
    const float* QR  = g_qr2[h] + (size_t)b * Tn * NRpad;
    const int*   Msk = mask + (size_t)b * Tn * Tn;
    float*       Out = gout + (size_t)h * Bn * Tn * Tn + (size_t)b * Tn * Tn;
    for (int it = threadIdx.x; it < BM * BN; it += 256) {
        const int row = it >> 7, c = it & 127;
        const int i = rowBase + row, j = colBase + c;
        int d = j - i; d = d < -Rn ? -Rn : (d > Rn ? Rn : d);
        float v = Cs[row * LDS_C + c] + QR[(size_t)i * NRpad + d + Rn];
        Out[(size_t)i * Tn + j] = Msk[(size_t)i * Tn + j] ? v : -1e18f;
    }
}

// --------------------------------- launch ----------------------------------
extern "C" void kernel_launch(void* const* d_in, const int* in_sizes, int n_in,
                              void* d_out, int out_size)
{
    (void)in_sizes; (void)n_in; (void)out_size;
    const float* repre  = (const float*)d_in[0];
    const int*   mask   = (const int*)  d_in[1];
    const float* st_Wq  = (const float*)d_in[2];
    const float* st_bq  = (const float*)d_in[3];
    const float* st_Wk  = (const float*)d_in[4];
    const float* st_bk  = (const float*)d_in[5];
    const float* st_rel = (const float*)d_in[6];
    const float* ed_Wq  = (const float*)d_in[7];
    const float* ed_bq  = (const float*)d_in[8];
    const float* ed_Wk  = (const float*)d_in[9];
    const float* ed_bk  = (const float*)d_in[10];
    const float* ed_rel = (const float*)d_in[11];
    float* out = (float*)d_out;

    static bool attr_set = false;
    if (!attr_set) {
        cudaFuncSetAttribute(proj_mma,   cudaFuncAttributeMaxDynamicSharedMemorySize, SMEM_BYTES);
        cudaFuncSetAttribute(qr_mma,     cudaFuncAttributeMaxDynamicSharedMemorySize, SMEM_BYTES);
        cudaFuncSetAttribute(scores_mma, cudaFuncAttributeMaxDynamicSharedMemorySize, SMEM_BYTES);
        attr_set = true;
    }

    convert_X  <<<Mrows * Dn / 512, 256>>>(repre);
    convert_Wt <<<dim3(32, 32, 4), dim3(32, 8)>>>(st_Wq, st_Wk, ed_Wq, ed_Wk);
    convert_rel<<<dim3(NRpad, 2), 256>>>(st_rel, ed_rel);

    proj_mma  <<<dim3(Dn/BN, Mrows/BM, 4), 256, SMEM_BYTES>>>(st_bq, st_bk, ed_bq, ed_bk);
    qr_mma    <<<dim3(NRpad/BN, Mrows/BM, 2), 256, SMEM_BYTES>>>();
    scores_mma<<<dim3(Tn/BN, Tn/BM, 8),    256, SMEM_BYTES>>>(mask, out);
}